// round 10
// baseline (speedup 1.0000x reference)
#include <cuda_runtime.h>
#include <cuda_bf16.h>
#include <cstdint>

// Problem constants (fixed by the dataset)
#define D_   64
#define H_   64
#define EF_  16
#define PC   192    // g_P row: [src-proj(+b_e1) | dst-proj | node-proj(+b_n1)]
#define TEE  128    // edges per tile (edge kernel)
#define NMAX 50000

__device__ float g_hneigh[(size_t)NMAX * H_];
__device__ float g_P[(size_t)NMAX * PC];

typedef unsigned int u32;

// Exact silu (2 MUFU)
__device__ __forceinline__ float silu_f(float x) {
    return __fdividef(x, 1.0f + __expf(-x));
}
// Fast silu (1 MUFU via hw tanh): x*sigmoid(x) = 0.5x*tanh(0.5x) + 0.5x
__device__ __forceinline__ float silu_fast(float x) {
    float t, hx = 0.5f * x;
    asm("tanh.approx.f32 %0, %1;" : "=f"(t) : "f"(hx));
    return fmaf(hx, t, hx);
}
__device__ __forceinline__ u32 smem_u32(const void* p) {
    u32 a;
    asm("{ .reg .u64 t; cvta.to.shared.u64 t, %1; cvt.u32.u64 %0, t; }"
        : "=r"(a) : "l"(p));
    return a;
}

__global__ void zero_hneigh(int n4) {
    float4 z = make_float4(0.f, 0.f, 0.f, 0.f);
    for (int i = blockIdx.x * blockDim.x + threadIdx.x; i < n4;
         i += gridDim.x * blockDim.x)
        reinterpret_cast<float4*>(g_hneigh)[i] = z;
}

extern __shared__ float smemf[];
extern __shared__ char smemc[];

// ---- mma helpers (sm_80-era PTX, portable; proven R5/R8) ----
__device__ __forceinline__ void ldsm_x4(u32& r0, u32& r1, u32& r2, u32& r3, u32 a) {
    asm volatile("ldmatrix.sync.aligned.m8n8.x4.shared.b16 {%0,%1,%2,%3}, [%4];"
                 : "=r"(r0), "=r"(r1), "=r"(r2), "=r"(r3) : "r"(a));
}
__device__ __forceinline__ void ldsm_x2(u32& r0, u32& r1, u32 a) {
    asm volatile("ldmatrix.sync.aligned.m8n8.x2.shared.b16 {%0,%1}, [%2];"
                 : "=r"(r0), "=r"(r1) : "r"(a));
}
__device__ __forceinline__ void mma16816(float* d, const u32* a, const u32* b) {
    asm volatile(
        "mma.sync.aligned.m16n8k16.row.col.f32.bf16.bf16.f32 "
        "{%0,%1,%2,%3}, {%4,%5,%6,%7}, {%8,%9}, {%0,%1,%2,%3};"
        : "+f"(d[0]), "+f"(d[1]), "+f"(d[2]), "+f"(d[3])
        : "r"(a[0]), "r"(a[1]), "r"(a[2]), "r"(a[3]), "r"(b[0]), "r"(b[1]));
}
__device__ __forceinline__ void bf16_split(float x, __nv_bfloat16& h, __nv_bfloat16& l) {
    h = __float2bfloat16(x);
    l = __float2bfloat16(x - __bfloat162float(h));
}
__device__ __forceinline__ u32 pack_hi2(float a, float b) {
    __nv_bfloat162 v; v.x = __float2bfloat16(a); v.y = __float2bfloat16(b);
    return *(u32*)&v;
}

#define MSTRIDE 144   // bytes per row of [*][64] bf16 tiles (M, W2)
#define ASTR    80    // bytes per row of K=32 bf16 tiles (A', W')

// ---------------------------------------------------------------------------
// Precompute: g_P[n] = [ nf@We1_src + b_e1 | nf@We1_dst | nf@Wn1_top + b_n1 ]
// ---------------------------------------------------------------------------
__global__ __launch_bounds__(256, 2) void pre_kernel(
    const float* __restrict__ node_feat,
    const float* __restrict__ W_e1, const float* __restrict__ b_e1,
    const float* __restrict__ W_n1, const float* __restrict__ b_n1, int N)
{
    float* Wp   = smemf;             // [64][192]
    float* Zs   = Wp + 64 * PC;      // [64][68]
    float* bsrc = Zs + 64 * 68;      // 64
    float* bn   = bsrc + 64;         // 64

    const int tid = threadIdx.x;
    const int tx  = tid & 31;
    const int ty  = tid >> 5;

    for (int i = tid; i < 64 * PC; i += 256) {
        int k = i / PC, c = i - k * PC;
        float v;
        if (c < 64)       v = W_e1[k * H_ + c];
        else if (c < 128) v = W_e1[(64 + k) * H_ + (c - 64)];
        else              v = W_n1[k * H_ + (c - 128)];
        Wp[i] = v;
    }
    if (tid < 64) { bsrc[tid] = b_e1[tid]; bn[tid] = b_n1[tid]; }

    const int ntiles = (N + 63) / 64;
    for (int tile = blockIdx.x; tile < ntiles; tile += gridDim.x) {
        const int n0 = tile * 64;
        __syncthreads();
        #pragma unroll
        for (int it = 0; it < 16; it++) {
            int idx = it * 256 + tid;
            int r = idx >> 6, k = idx & 63;
            int n = n0 + r;
            Zs[r * 68 + k] = (n < N) ? node_feat[n * D_ + k] : 0.f;
        }
        __syncthreads();

        float acc[8][4], accB[8][2];
        #pragma unroll
        for (int i = 0; i < 8; i++) {
            acc[i][0] = acc[i][1] = acc[i][2] = acc[i][3] = 0.f;
            accB[i][0] = accB[i][1] = 0.f;
        }
        const float* zb = &Zs[(ty * 8) * 68];
        #pragma unroll 4
        for (int k = 0; k < 64; k++) {
            const float4 w = *reinterpret_cast<const float4*>(&Wp[k * PC + tx * 4]);
            const float2 wb = *reinterpret_cast<const float2*>(&Wp[k * PC + 128 + tx * 2]);
            #pragma unroll
            for (int i = 0; i < 8; i++) {
                float z = zb[i * 68 + k];
                acc[i][0] += z * w.x; acc[i][1] += z * w.y;
                acc[i][2] += z * w.z; acc[i][3] += z * w.w;
                accB[i][0] += z * wb.x; accB[i][1] += z * wb.y;
            }
        }
        #pragma unroll
        for (int i = 0; i < 8; i++) {
            int n = n0 + ty * 8 + i;
            if (n < N) {
                float4 v = make_float4(acc[i][0], acc[i][1], acc[i][2], acc[i][3]);
                if (tx < 16) {
                    v.x += bsrc[tx * 4 + 0]; v.y += bsrc[tx * 4 + 1];
                    v.z += bsrc[tx * 4 + 2]; v.w += bsrc[tx * 4 + 3];
                }
                *reinterpret_cast<float4*>(&g_P[(size_t)n * PC + tx * 4]) = v;
                float2 vb = make_float2(accB[i][0] + bn[tx * 2],
                                        accB[i][1] + bn[tx * 2 + 1]);
                *reinterpret_cast<float2*>(&g_P[(size_t)n * PC + 128 + tx * 2]) = vb;
            }
        }
    }
}

// ---------------------------------------------------------------------------
// Edge kernel, fully tensorized:
//  stage1: acc = A'@W'^T (A'=[a|rad|0] K=32 split-bf16, 3 products)
//          + fragment-layout gathers (P_s[src] + P_d[dst])  -> silu -> M tiles
//  stage2: M @ W2^T (split-bf16, 3 products) -> +b2, silu -> Msg -> REDG scatter
// ---------------------------------------------------------------------------
#define EO_RAD  0          // 128 f
#define EO_SRC  512        // 128 i
#define EO_DST  1024       // 128 i
#define EO_B2   1536       // 64 f
#define EO_W2HI 1792       // 64 x MSTRIDE
#define EO_W2LO 11008      // 64 x MSTRIDE
#define EO_WPHI 20224      // 64 x ASTR   (W' = [Wa^T | wr], [n][k])
#define EO_WPLO 25344      // 64 x ASTR
#define EO_APHI 30464      // 128 x ASTR  (A' = [a | rad | 0], [r][k])
#define EO_APLO 40704      // 128 x ASTR
#define EO_MHI  50944      // 128 x MSTRIDE
#define EO_MLO  69376      // 128 x MSTRIDE
#define EO_MSG  EO_MHI     // alias: msg tile [128][68] f
#define EO_TOT  87808

__global__ __launch_bounds__(256, 2) void edge_kernel(
    const float* __restrict__ coord, const float* __restrict__ edge_feat,
    const int* __restrict__ src, const int* __restrict__ dst,
    const float* __restrict__ W_e1, const float* __restrict__ W_e2,
    const float* __restrict__ b_e2, int E)
{
    char* smem = smemc;
    const u32 sb = smem_u32(smem);
    float* rad  = (float*)(smem + EO_RAD);
    int*   sSrc = (int*)(smem + EO_SRC);
    int*   sDst = (int*)(smem + EO_DST);
    float* b2s  = (float*)(smem + EO_B2);
    float* Msg  = (float*)(smem + EO_MSG);

    const int tid = threadIdx.x;
    const int wid = tid >> 5;
    const int lid = tid & 31;

    // --- one-time init ---
    // zero W' + A' regions (covers k=17..31 padding permanently)
    for (int i = tid; i < (EO_MHI - EO_WPHI) / 4; i += 256)
        ((u32*)(smem + EO_WPHI))[i] = 0;
    if (tid < H_) b2s[tid] = b_e2[tid];
    // W2^T split hi/lo at [n][k], MSTRIDE rows
    for (int i = tid; i < H_ * H_; i += 256) {
        int k = i >> 6, n = i & 63;
        __nv_bfloat16 hi, lo; bf16_split(W_e2[i], hi, lo);
        *(__nv_bfloat16*)(smem + EO_W2HI + n * MSTRIDE + k * 2) = hi;
        *(__nv_bfloat16*)(smem + EO_W2LO + n * MSTRIDE + k * 2) = lo;
    }
    __syncthreads();   // zeros visible before W' fill
    // W'[n][k]: k<16 -> Wa^T = W_e1[(129+k)*64+n]; k=16 -> wr = W_e1[128*64+n]
    for (int i = tid; i < 64 * 16; i += 256) {
        int n = i >> 4, k = i & 15;
        __nv_bfloat16 h, l; bf16_split(W_e1[(129 + k) * H_ + n], h, l);
        *(__nv_bfloat16*)(smem + EO_WPHI + n * ASTR + k * 2) = h;
        *(__nv_bfloat16*)(smem + EO_WPLO + n * ASTR + k * 2) = l;
    }
    if (tid < 64) {
        __nv_bfloat16 h, l; bf16_split(W_e1[128 * H_ + tid], h, l);
        *(__nv_bfloat16*)(smem + EO_WPHI + tid * ASTR + 32) = h;
        *(__nv_bfloat16*)(smem + EO_WPLO + tid * ASTR + 32) = l;
    }

    // fragment coordinates (fixed per thread)
    const int m0  = wid * 16;
    const int rA  = m0 + (lid >> 2);
    const int rB  = rA + 8;
    const int cfr = (lid & 3) * 2;
    const u32 aoff1 = (u32)((m0 + (lid & 15)) * ASTR + (lid >> 4) * 16);
    const u32 boff1 = (u32)((lid & 7) * ASTR + ((lid >> 3) & 1) * 16);
    const u32 aoff2 = (u32)((m0 + (lid & 15)) * MSTRIDE + (lid >> 4) * 16);
    const u32 boff2 = (u32)((lid & 7) * MSTRIDE + ((lid >> 3) & 1) * 16);

    const int ntiles = (E + TEE - 1) / TEE;
    for (int tile = blockIdx.x; tile < ntiles; tile += gridDim.x) {
        const int e0 = tile * TEE;
        __syncthreads();   // prior tile's reads of A'/rad/idx + scatter done

        // Phase A1: indices + radial (radial also into A' k=16)
        if (tid < TEE) {
            int e = e0 + tid;
            int s = 0, d = 0;
            float radial = 0.f;
            if (e < E) {
                s = src[e]; d = dst[e];
                float dx = coord[3 * s + 0] - coord[3 * d + 0];
                float dy = coord[3 * s + 1] - coord[3 * d + 1];
                float dz = coord[3 * s + 2] - coord[3 * d + 2];
                radial = dx * dx + dy * dy + dz * dz;
            }
            sSrc[tid] = s; sDst[tid] = d; rad[tid] = radial;
            __nv_bfloat16 h, l; bf16_split(radial, h, l);
            *(__nv_bfloat16*)(smem + EO_APHI + tid * ASTR + 32) = h;
            *(__nv_bfloat16*)(smem + EO_APLO + tid * ASTR + 32) = l;
        }
        // Phase A2: edge_feat -> A' k=0..15 (coalesced, 8 floats/thread)
        {
            int r = tid >> 1, k8 = (tid & 1) * 8;
            int e = e0 + r;
            float4 v0 = make_float4(0.f, 0.f, 0.f, 0.f), v1 = v0;
            if (e < E) {
                v0 = *reinterpret_cast<const float4*>(&edge_feat[(size_t)e * EF_ + k8]);
                v1 = *reinterpret_cast<const float4*>(&edge_feat[(size_t)e * EF_ + k8 + 4]);
            }
            __nv_bfloat16 h, l;
            u32 hi0, hi1, hi2, hi3, lo0, lo1, lo2, lo3;
            bf16_split(v0.x, h, l); __nv_bfloat162 t0h, t0l; t0h.x = h; t0l.x = l;
            bf16_split(v0.y, h, l); t0h.y = h; t0l.y = l;
            hi0 = *(u32*)&t0h; lo0 = *(u32*)&t0l;
            bf16_split(v0.z, h, l); t0h.x = h; t0l.x = l;
            bf16_split(v0.w, h, l); t0h.y = h; t0l.y = l;
            hi1 = *(u32*)&t0h; lo1 = *(u32*)&t0l;
            bf16_split(v1.x, h, l); t0h.x = h; t0l.x = l;
            bf16_split(v1.y, h, l); t0h.y = h; t0l.y = l;
            hi2 = *(u32*)&t0h; lo2 = *(u32*)&t0l;
            bf16_split(v1.z, h, l); t0h.x = h; t0l.x = l;
            bf16_split(v1.w, h, l); t0h.y = h; t0l.y = l;
            hi3 = *(u32*)&t0h; lo3 = *(u32*)&t0l;
            *(uint2*)(smem + EO_APHI + r * ASTR + k8 * 2) = make_uint2(hi0, hi1);
            *(uint2*)(smem + EO_APHI + r * ASTR + k8 * 2 + 8) = make_uint2(hi2, hi3);
            *(uint2*)(smem + EO_APLO + r * ASTR + k8 * 2) = make_uint2(lo0, lo1);
            *(uint2*)(smem + EO_APLO + r * ASTR + k8 * 2 + 8) = make_uint2(lo2, lo3);
        }
        __syncthreads();

        // Fragment-layout gathers: psum = P_s[src] + P_d[dst] (issued early)
        float2 psA[8], psB[8];
        {
            const int sA = sSrc[rA], dA = sDst[rA];
            const int sB = sSrc[rB], dB = sDst[rB];
            #pragma unroll
            for (int nt = 0; nt < 8; nt++) {
                int c = nt * 8 + cfr;
                float2 a1 = *reinterpret_cast<const float2*>(&g_P[(size_t)sA * PC + c]);
                float2 a2 = *reinterpret_cast<const float2*>(&g_P[(size_t)dA * PC + 64 + c]);
                float2 b1 = *reinterpret_cast<const float2*>(&g_P[(size_t)sB * PC + c]);
                float2 b2 = *reinterpret_cast<const float2*>(&g_P[(size_t)dB * PC + 64 + c]);
                psA[nt] = make_float2(a1.x + a2.x, a1.y + a2.y);
                psB[nt] = make_float2(b1.x + b2.x, b1.y + b2.y);
            }
        }

        // MMA1: acc = A' @ W'^T (K=32, 2 k-steps, 3 split products)
        float acc[8][4];
        #pragma unroll
        for (int nt = 0; nt < 8; nt++)
            acc[nt][0] = acc[nt][1] = acc[nt][2] = acc[nt][3] = 0.f;
        #pragma unroll
        for (int j = 0; j < 2; j++) {
            u32 ah[4], al[4];
            ldsm_x4(ah[0], ah[1], ah[2], ah[3], sb + EO_APHI + aoff1 + j * 32);
            ldsm_x4(al[0], al[1], al[2], al[3], sb + EO_APLO + aoff1 + j * 32);
            #pragma unroll
            for (int nt = 0; nt < 8; nt++) {
                u32 bh[2], bl[2];
                u32 boff = (u32)(nt * 8 * ASTR) + boff1 + j * 32;
                ldsm_x2(bh[0], bh[1], sb + EO_WPHI + boff);
                ldsm_x2(bl[0], bl[1], sb + EO_WPLO + boff);
                mma16816(acc[nt], ah, bh);
                mma16816(acc[nt], ah, bl);
                mma16816(acc[nt], al, bh);
            }
        }

        // Fold gathers, silu, split -> M tiles (MHI/MLO are a distinct region)
        #pragma unroll
        for (int nt = 0; nt < 8; nt++) {
            int c = nt * 8 + cfr;
            float v0 = silu_fast(acc[nt][0] + psA[nt].x);
            float v1 = silu_fast(acc[nt][1] + psA[nt].y);
            float v2 = silu_fast(acc[nt][2] + psB[nt].x);
            float v3 = silu_fast(acc[nt][3] + psB[nt].y);
            __nv_bfloat16 h0, h1, h2, h3, l0, l1, l2, l3;
            bf16_split(v0, h0, l0); bf16_split(v1, h1, l1);
            bf16_split(v2, h2, l2); bf16_split(v3, h3, l3);
            __nv_bfloat162 HA; HA.x = h0; HA.y = h1;
            __nv_bfloat162 HB; HB.x = h2; HB.y = h3;
            __nv_bfloat162 LA; LA.x = l0; LA.y = l1;
            __nv_bfloat162 LB; LB.x = l2; LB.y = l3;
            *(u32*)(smem + EO_MHI + rA * MSTRIDE + c * 2) = *(u32*)&HA;
            *(u32*)(smem + EO_MHI + rB * MSTRIDE + c * 2) = *(u32*)&HB;
            *(u32*)(smem + EO_MLO + rA * MSTRIDE + c * 2) = *(u32*)&LA;
            *(u32*)(smem + EO_MLO + rB * MSTRIDE + c * 2) = *(u32*)&LB;
        }
        __syncthreads();

        // MMA2: msg_pre = M @ W2^T (K=64, 4 k-steps, 3 split products)
        float acc2[8][4];
        #pragma unroll
        for (int nt = 0; nt < 8; nt++)
            acc2[nt][0] = acc2[nt][1] = acc2[nt][2] = acc2[nt][3] = 0.f;
        #pragma unroll
        for (int j = 0; j < 4; j++) {
            u32 ah[4], al[4];
            ldsm_x4(ah[0], ah[1], ah[2], ah[3], sb + EO_MHI + aoff2 + j * 32);
            ldsm_x4(al[0], al[1], al[2], al[3], sb + EO_MLO + aoff2 + j * 32);
            #pragma unroll
            for (int nt = 0; nt < 8; nt++) {
                u32 bh[2], bl[2];
                u32 boff = (u32)(nt * 8 * MSTRIDE) + boff2 + j * 32;
                ldsm_x2(bh[0], bh[1], sb + EO_W2HI + boff);
                ldsm_x2(bl[0], bl[1], sb + EO_W2LO + boff);
                mma16816(acc2[nt], ah, bh);
                mma16816(acc2[nt], ah, bl);
                mma16816(acc2[nt], al, bh);
            }
        }
        __syncthreads();   // M reads done -> Msg may alias MHI

        // Epilogue A: bias + silu -> Msg tile
        #pragma unroll
        for (int nt = 0; nt < 8; nt++) {
            int c = nt * 8 + cfr;
            const float bb0 = b2s[c], bb1 = b2s[c + 1];
            float2 vA = make_float2(silu_fast(acc2[nt][0] + bb0),
                                    silu_fast(acc2[nt][1] + bb1));
            float2 vB = make_float2(silu_fast(acc2[nt][2] + bb0),
                                    silu_fast(acc2[nt][3] + bb1));
            *reinterpret_cast<float2*>(&Msg[rA * 68 + c]) = vA;
            *reinterpret_cast<float2*>(&Msg[rB * 68 + c]) = vB;
        }
        __syncthreads();

        // Epilogue B: row-coalesced v4 scatter
        {
            const int nvalid = min(TEE, E - e0);
            #pragma unroll
            for (int it = 0; it < 8; it++) {
                int slot = it * 256 + tid;
                int r = slot >> 4, ch = slot & 15;
                if (r < nvalid) {
                    float4 v = *reinterpret_cast<const float4*>(&Msg[r * 68 + ch * 4]);
                    float* p = &g_hneigh[(size_t)sDst[r] * H_ + ch * 4];
                    asm volatile("red.global.add.v4.f32 [%0], {%1,%2,%3,%4};"
                                 :: "l"(p), "f"(v.x), "f"(v.y), "f"(v.z), "f"(v.w)
                                 : "memory");
                }
            }
        }
    }
}

// ---------------------------------------------------------------------------
// Node kernel, tensorized (R8 winner, unchanged)
// ---------------------------------------------------------------------------
#define NO_W1HI 0
#define NO_W1LO 9216
#define NO_W2HI 18432
#define NO_W2LO 27648
#define NO_B2   36864
#define NO_ZHI  37120
#define NO_ZLO  55552
#define NO_TOT  73984

__global__ __launch_bounds__(256, 2) void node_kernel(
    const float* __restrict__ W_n1, const float* __restrict__ W_n2,
    const float* __restrict__ b_n2, float* __restrict__ out, int N)
{
    char* smem = smemc;
    const u32 sb = smem_u32(smem);
    float* b2s = (float*)(smem + NO_B2);

    const int tid = threadIdx.x;
    const int wid = tid >> 5;
    const int lid = tid & 31;

    for (int i = tid; i < 64 * 64; i += 256) {
        int c = i >> 6, k = i & 63;
        __nv_bfloat16 h, l;
        bf16_split(W_n1[(64 + k) * 64 + c], h, l);
        *(__nv_bfloat16*)(smem + NO_W1HI + c * MSTRIDE + k * 2) = h;
        *(__nv_bfloat16*)(smem + NO_W1LO + c * MSTRIDE + k * 2) = l;
        bf16_split(W_n2[k * 64 + c], h, l);
        *(__nv_bfloat16*)(smem + NO_W2HI + c * MSTRIDE + k * 2) = h;
        *(__nv_bfloat16*)(smem + NO_W2LO + c * MSTRIDE + k * 2) = l;
    }
    if (tid < 64) b2s[tid] = b_n2[tid];

    const int m0  = wid * 16;
    const int rA  = m0 + (lid >> 2);
    const int rB  = rA + 8;
    const int cfr = (lid & 3) * 2;
    const u32 aoff  = (u32)((m0 + (lid & 15)) * MSTRIDE + (lid >> 4) * 16);
    const u32 boffR = (u32)((lid & 7) * MSTRIDE + ((lid >> 3) & 1) * 16);

    const int ntiles = (N + 127) / 128;
    for (int tile = blockIdx.x; tile < ntiles; tile += gridDim.x) {
        const int n0 = tile * 128;
        __syncthreads();

        #pragma unroll
        for (int it = 0; it < 8; it++) {
            int idx = it * 256 + tid;
            int r = idx >> 4, k4 = (idx & 15) * 4;
            int n = n0 + r;
            float4 v = (n < N)
                ? *reinterpret_cast<const float4*>(&g_hneigh[(size_t)n * H_ + k4])
                : make_float4(0.f, 0.f, 0.f, 0.f);
            __nv_bfloat16 h0, h1, h2, h3, l0, l1, l2, l3;
            bf16_split(v.x, h0, l0); bf16_split(v.y, h1, l1);
            bf16_split(v.z, h2, l2); bf16_split(v.w, h3, l3);
            __nv_bfloat162 H01; H01.x = h0; H01.y = h1;
            __nv_bfloat162 H23; H23.x = h2; H23.y = h3;
            __nv_bfloat162 L01; L01.x = l0; L01.y = l1;
            __nv_bfloat162 L23; L23.x = l2; L23.y = l3;
            *(uint2*)(smem + NO_ZHI + r * MSTRIDE + k4 * 2) =
                make_uint2(*(u32*)&H01, *(u32*)&H23);
            *(uint2*)(smem + NO_ZLO + r * MSTRIDE + k4 * 2) =
                make_uint2(*(u32*)&L01, *(u32*)&L23);
        }
        __syncthreads();

        float acc[8][4];
        {
            const int nA = n0 + rA, nB = n0 + rB;
            #pragma unroll
            for (int nt = 0; nt < 8; nt++) {
                int c = nt * 8 + cfr;
                float2 pA = (nA < N)
                    ? *reinterpret_cast<const float2*>(&g_P[(size_t)nA * PC + 128 + c])
                    : make_float2(0.f, 0.f);
                float2 pB = (nB < N)
                    ? *reinterpret_cast<const float2*>(&g_P[(size_t)nB * PC + 128 + c])
                    : make_float2(0.f, 0.f);
                acc[nt][0] = pA.x; acc[nt][1] = pA.y;
                acc[nt][2] = pB.x; acc[nt][3] = pB.y;
            }
            #pragma unroll
            for (int j = 0; j < 4; j++) {
                u32 ah[4], al[4];
                ldsm_x4(ah[0], ah[1], ah[2], ah[3], sb + NO_ZHI + aoff + j * 32);
                ldsm_x4(al[0], al[1], al[2], al[3], sb + NO_ZLO + aoff + j * 32);
                #pragma unroll
                for (int nt = 0; nt < 8; nt++) {
                    u32 bh[2], bl[2];
                    u32 boff = (u32)(nt * 8 * MSTRIDE) + boffR + j * 32;
                    ldsm_x2(bh[0], bh[1], sb + NO_W1HI + boff);
                    ldsm_x2(bl[0], bl[1], sb + NO_W1LO + boff);
                    mma16816(acc[nt], ah, bh);
                    mma16816(acc[nt], ah, bl);
                    mma16816(acc[nt], al, bh);
                }
            }
        }
        __syncthreads();

        #pragma unroll
        for (int nt = 0; nt < 8; nt++) {
            int c = nt * 8 + cfr;
            float v0 = silu_f(acc[nt][0]);
            float v1 = silu_f(acc[nt][1]);
            float v2 = silu_f(acc[nt][2]);
            float v3 = silu_f(acc[nt][3]);
            __nv_bfloat16 h0, h1, h2, h3, l0, l1, l2, l3;
            bf16_split(v0, h0, l0); bf16_split(v1, h1, l1);
            bf16_split(v2, h2, l2); bf16_split(v3, h3, l3);
            __nv_bfloat162 HA; HA.x = h0; HA.y = h1;
            __nv_bfloat162 HB; HB.x = h2; HB.y = h3;
            __nv_bfloat162 LA; LA.x = l0; LA.y = l1;
            __nv_bfloat162 LB; LB.x = l2; LB.y = l3;
            *(u32*)(smem + NO_ZHI + rA * MSTRIDE + c * 2) = *(u32*)&HA;
            *(u32*)(smem + NO_ZHI + rB * MSTRIDE + c * 2) = *(u32*)&HB;
            *(u32*)(smem + NO_ZLO + rA * MSTRIDE + c * 2) = *(u32*)&LA;
            *(u32*)(smem + NO_ZLO + rB * MSTRIDE + c * 2) = *(u32*)&LB;
        }
        __syncthreads();

        float acc2[8][4];
        {
            #pragma unroll
            for (int nt = 0; nt < 8; nt++) {
                int c = nt * 8 + cfr;
                float b0 = b2s[c], b1 = b2s[c + 1];
                acc2[nt][0] = b0; acc2[nt][1] = b1;
                acc2[nt][2] = b0; acc2[nt][3] = b1;
            }
            #pragma unroll
            for (int j = 0; j < 4; j++) {
                u32 ah[4], al[4];
                ldsm_x4(ah[0], ah[1], ah[2], ah[3], sb + NO_ZHI + aoff + j * 32);
                ldsm_x4(al[0], al[1], al[2], al[3], sb + NO_ZLO + aoff + j * 32);
                #pragma unroll
                for (int nt = 0; nt < 8; nt++) {
                    u32 bh[2], bl[2];
                    u32 boff = (u32)(nt * 8 * MSTRIDE) + boffR + j * 32;
                    ldsm_x2(bh[0], bh[1], sb + NO_W2HI + boff);
                    ldsm_x2(bl[0], bl[1], sb + NO_W2LO + boff);
                    mma16816(acc2[nt], ah, bh);
                    mma16816(acc2[nt], ah, bl);
                    mma16816(acc2[nt], al, bh);
                }
            }
        }

        {
            const int nA = n0 + rA, nB = n0 + rB;
            #pragma unroll
            for (int nt = 0; nt < 8; nt++) {
                int c = nt * 8 + cfr;
                if (nA < N)
                    *reinterpret_cast<float2*>(&out[(size_t)nA * D_ + c]) =
                        make_float2(acc2[nt][0], acc2[nt][1]);
                if (nB < N)
                    *reinterpret_cast<float2*>(&out[(size_t)nB * D_ + c]) =
                        make_float2(acc2[nt][2], acc2[nt][3]);
            }
        }
    }
}

extern "C" void kernel_launch(void* const* d_in, const int* in_sizes, int n_in,
                              void* d_out, int out_size)
{
    const float* node_feat = (const float*)d_in[0];
    const float* coord     = (const float*)d_in[1];
    const float* edge_feat = (const float*)d_in[2];
    const int*   src       = (const int*)d_in[3];
    const int*   dst       = (const int*)d_in[4];
    const float* W_e1      = (const float*)d_in[5];
    const float* b_e1      = (const float*)d_in[6];
    const float* W_e2      = (const float*)d_in[7];
    const float* b_e2      = (const float*)d_in[8];
    const float* W_n1      = (const float*)d_in[9];
    const float* b_n1      = (const float*)d_in[10];
    const float* W_n2      = (const float*)d_in[11];
    const float* b_n2      = (const float*)d_in[12];
    float* out = (float*)d_out;

    const int N = in_sizes[0] / D_;
    const int E = in_sizes[3];

    const size_t smemP = (size_t)(64 * PC + 64 * 68 + 128) * 4;
    const size_t smemE = EO_TOT;
    const size_t smemN = NO_TOT;

    cudaFuncSetAttribute(pre_kernel,
                         cudaFuncAttributeMaxDynamicSharedMemorySize, (int)smemP);
    cudaFuncSetAttribute(edge_kernel,
                         cudaFuncAttributeMaxDynamicSharedMemorySize, (int)smemE);
    cudaFuncSetAttribute(node_kernel,
                         cudaFuncAttributeMaxDynamicSharedMemorySize, (int)smemN);

    zero_hneigh<<<512, 256>>>(N * H_ / 4);
    pre_kernel<<<296, 256, smemP>>>(node_feat, W_e1, b_e1, W_n1, b_n1, N);
    edge_kernel<<<296, 256, smemE>>>(coord, edge_feat, src, dst,
                                     W_e1, W_e2, b_e2, E);
    node_kernel<<<296, 256, smemN>>>(W_n1, W_n2, b_n2, out, N);
}